// round 8
// baseline (speedup 1.0000x reference)
#include <cuda_runtime.h>
#include <cuda_bf16.h>
#include <cstdint>

#define THREADS 512

// ---- smem layout (bytes) ----
#define A_HI   0          // bf16 [128 rows][168] (160 data + pad), stride 336 B
#define A_LO   43008
#define B_HI   86016      // bf16 [64 rows][160], stride 320 B
#define B_LO   106496
#define HALO   126976     // fp32 [16 ic][10 r][18 c]
#define DST    138496     // fp32 [128 p][68]
#define SMEM_BYTES 173312
#define A_STR  336
#define B_STR  320
#define DST_STR 68

// Global phase-weight planes: [g(8)][n(64)][k(160)] bf16
__device__ unsigned short g_Bh[8 * 64 * 160];
__device__ unsigned short g_Bl[8 * 64 * 160];

__device__ __forceinline__ uint32_t smem_u32(const void* p) {
    uint32_t a;
    asm("{ .reg .u64 t; cvta.to.shared.u64 t, %1; cvt.u32.u64 %0, t; }" : "=r"(a) : "l"(p));
    return a;
}
__device__ __forceinline__ void ldmx4(uint32_t& r0, uint32_t& r1, uint32_t& r2, uint32_t& r3,
                                      uint32_t addr) {
    asm volatile("ldmatrix.sync.aligned.m8n8.x4.shared.b16 {%0,%1,%2,%3}, [%4];"
                 : "=r"(r0), "=r"(r1), "=r"(r2), "=r"(r3) : "r"(addr));
}
__device__ __forceinline__ void mma_bf16(float* c, uint32_t a0, uint32_t a1, uint32_t a2,
                                         uint32_t a3, uint32_t b0, uint32_t b1) {
    asm volatile(
        "mma.sync.aligned.m16n8k16.row.col.f32.bf16.bf16.f32 "
        "{%0,%1,%2,%3}, {%4,%5,%6,%7}, {%8,%9}, {%0,%1,%2,%3};"
        : "+f"(c[0]), "+f"(c[1]), "+f"(c[2]), "+f"(c[3])
        : "r"(a0), "r"(a1), "r"(a2), "r"(a3), "r"(b0), "r"(b1));
}
// truncation hi/lo split: hi = top-16-bits(v) as bf16 (exact residual), lo = rn(v - hi)
__device__ __forceinline__ void split_pair(float v0, float v1, uint32_t& hi, uint32_t& lo) {
    uint32_t u0 = __float_as_uint(v0), u1 = __float_as_uint(v1);
    hi = (u0 >> 16) | (u1 & 0xffff0000u);
    float l0 = v0 - __uint_as_float(u0 & 0xffff0000u);
    float l1 = v1 - __uint_as_float(u1 & 0xffff0000u);
    __nv_bfloat162 lp = __float22bfloat162_rn(make_float2(l0, l1));
    lo = *(uint32_t*)&lp;
}

// ---------------- prep: phase-decomposed weights (R1 math), bf16 hi/lo ----------------
__global__ void prep_weff(const float* __restrict__ f, const float* __restrict__ w) {
    int idx = blockIdx.x * blockDim.x + threadIdx.x;
    if (idx >= 8 * 16 * 16 * 10) return;
    int tap = idx % 10;
    int ic = (idx / 10) % 16;
    int oc = (idx / 160) % 16;
    int g = idx / 2560;
    float v[4] = {0.f, 0.f, 0.f, 0.f};
    if (tap < 9) {
        int ky = tap / 3, kx = tap % 3;
        float gf[4];
#pragma unroll
        for (int a = 0; a < 4; ++a) gf[a] = 2.0f * f[3 - a];
        int oc_g = g * 16 + oc;
#pragma unroll
        for (int kh = 0; kh < 3; ++kh) {
            int ay0i = 2 * ky + 1 - kh, ay1i = 2 * ky - kh;
            float Ay0 = (ay0i >= 0 && ay0i < 4) ? gf[ay0i] : 0.f;
            float Ay1 = (ay1i >= 0 && ay1i < 4) ? gf[ay1i] : 0.f;
#pragma unroll
            for (int kw = 0; kw < 3; ++kw) {
                int ax0i = 2 * kx + 1 - kw, ax1i = 2 * kx - kw;
                float Ax0 = (ax0i >= 0 && ax0i < 4) ? gf[ax0i] : 0.f;
                float Ax1 = (ax1i >= 0 && ax1i < 4) ? gf[ax1i] : 0.f;
                float wv = w[((oc_g * 16 + ic) * 3 + kh) * 3 + kw];
                v[0] += wv * Ay0 * Ax0;   // py0 px0
                v[1] += wv * Ay0 * Ax1;   // py0 px1
                v[2] += wv * Ay1 * Ax0;   // py1 px0
                v[3] += wv * Ay1 * Ax1;   // py1 px1
            }
        }
    }
    int k = ic * 10 + tap;
#pragma unroll
    for (int ph = 0; ph < 4; ++ph) {
        int nn = ph * 16 + oc;
        size_t gi = ((size_t)g * 64 + nn) * 160 + k;
        float val = v[ph];
        uint32_t u = __float_as_uint(val);
        unsigned short h = (unsigned short)(u >> 16);
        float lo = val - __uint_as_float(u & 0xffff0000u);
        __nv_bfloat16 lb = __float2bfloat16_rn(lo);
        g_Bh[gi] = h;
        g_Bl[gi] = *(unsigned short*)&lb;
    }
}

// ---------------- main kernel: im2col -> mma.sync bf16 3-pass -> epilogue ----------------
__global__ __launch_bounds__(THREADS, 1)
void conv_mma_kernel(const float* __restrict__ x, float* __restrict__ out) {
    extern __shared__ char smem[];
    const uint32_t sbase = smem_u32(smem);
    const int tid = threadIdx.x;
    const int wid = tid >> 5, lane = tid & 31;

    const int tileid = blockIdx.x;          // 512 tiles: 32 row-tiles x 16 col-tiles
    const int g = blockIdx.y, n = blockIdx.z;
    const int m0 = (tileid >> 4) * 8;       // low-res row origin (8 rows)
    const int c0 = (tileid & 15) * 16;      // low-res col origin (16 cols)

    float* halo = (float*)(smem + HALO);

    // ---- halo: [16 ic][10 r][18 c] fp32, zero padded ----
    const float* xg = x + ((size_t)(n * 128 + g * 16)) * 65536;
    for (int i = tid; i < 16 * 10 * 18; i += THREADS) {
        int c = i % 18;
        int r = (i / 18) % 10;
        int ic = i / 180;
        int gm = m0 - 1 + r, gq = c0 - 1 + c;
        float v = (gm >= 0 && gm < 256 && gq >= 0 && gq < 256)
                    ? xg[ic * 65536 + gm * 256 + gq] : 0.f;
        halo[i] = v;
    }
    // ---- B: raw copy of this group's hi/lo planes (64 x 160 bf16 = 20480 B each) ----
    {
        const float4* bh = (const float4*)(g_Bh + (size_t)g * 10240);
        const float4* bl = (const float4*)(g_Bl + (size_t)g * 10240);
        float4* sh = (float4*)(smem + B_HI);
        float4* sl = (float4*)(smem + B_LO);
        for (int i = tid; i < 1280; i += THREADS) { sh[i] = bh[i]; sl[i] = bl[i]; }
    }
    __syncthreads();

    // ---- im2col: p = tid>>2 (0..127), 4 ic per thread (ic = (tid&3) + 4*iq) ----
    {
        const int p = tid >> 2;
        const int r = p >> 4, c = p & 15;
        char* arow_hi = smem + A_HI + p * A_STR;
        char* arow_lo = smem + A_LO + p * A_STR;
#pragma unroll
        for (int iq = 0; iq < 4; ++iq) {
            int ic = (tid & 3) + iq * 4;
            const float* hp = halo + (ic * 10 + r) * 18 + c;
            float v0 = hp[0],  v1 = hp[1],  v2 = hp[2];
            float v3 = hp[18], v4 = hp[19], v5 = hp[20];
            float v6 = hp[36], v7 = hp[37], v8 = hp[38];
            uint32_t h, l;
            int ko = ic * 20;                       // byte offset (ic*10 bf16)
            split_pair(v0, v1, h, l);
            *(uint32_t*)(arow_hi + ko) = h;      *(uint32_t*)(arow_lo + ko) = l;
            split_pair(v2, v3, h, l);
            *(uint32_t*)(arow_hi + ko + 4) = h;  *(uint32_t*)(arow_lo + ko + 4) = l;
            split_pair(v4, v5, h, l);
            *(uint32_t*)(arow_hi + ko + 8) = h;  *(uint32_t*)(arow_lo + ko + 8) = l;
            split_pair(v6, v7, h, l);
            *(uint32_t*)(arow_hi + ko + 12) = h; *(uint32_t*)(arow_lo + ko + 12) = l;
            split_pair(v8, 0.f, h, l);
            *(uint32_t*)(arow_hi + ko + 16) = h; *(uint32_t*)(arow_lo + ko + 16) = l;
        }
    }
    __syncthreads();

    // ---- mma: warp (ws = wid>>1 strip of 16 rows, wn = wid&1 n-half of 32) ----
    float acc[4][4];
#pragma unroll
    for (int t = 0; t < 4; ++t)
#pragma unroll
        for (int e = 0; e < 4; ++e) acc[t][e] = 0.f;

    {
        const int ws = wid >> 1, wn = wid & 1;
        const uint32_t abase = sbase + A_HI + (ws * 16 + (lane & 15)) * A_STR + (lane >> 4) * 16;
        const uint32_t bbase = sbase + B_HI
            + (wn * 32 + 8 * (lane >> 4) + (lane & 7)) * B_STR + ((lane >> 3) & 1) * 16;
        const uint32_t bbase2 = bbase + 16 * B_STR;

#pragma unroll 1
        for (int pass = 0; pass < 3; ++pass) {
            const uint32_t aoff = (pass == 2) ? (A_LO - A_HI) : 0u;
            const uint32_t boff = (pass == 1) ? (B_LO - B_HI) : 0u;
#pragma unroll
            for (int s = 0; s < 10; ++s) {
                uint32_t a0, a1, a2, a3;
                ldmx4(a0, a1, a2, a3, abase + aoff + s * 32);
                uint32_t b0, b1, b2, b3;
                ldmx4(b0, b1, b2, b3, bbase + boff + s * 32);
                mma_bf16(acc[0], a0, a1, a2, a3, b0, b1);
                mma_bf16(acc[1], a0, a1, a2, a3, b2, b3);
                uint32_t b4, b5, b6, b7;
                ldmx4(b4, b5, b6, b7, bbase2 + boff + s * 32);
                mma_bf16(acc[2], a0, a1, a2, a3, b4, b5);
                mma_bf16(acc[3], a0, a1, a2, a3, b6, b7);
            }
        }
    }

    // ---- stage D to smem ----
    {
        const int ws = wid >> 1, wn = wid & 1;
        float* dst = (float*)(smem + DST);
        int row0 = ws * 16 + (lane >> 2);
        int colb = wn * 32 + (lane & 3) * 2;
#pragma unroll
        for (int t = 0; t < 4; ++t) {
            *(float2*)(dst + row0 * DST_STR + colb + t * 8) = make_float2(acc[t][0], acc[t][1]);
            *(float2*)(dst + (row0 + 8) * DST_STR + colb + t * 8) = make_float2(acc[t][2], acc[t][3]);
        }
    }
    __syncthreads();

    // ---- epilogue: phase-interleaved coalesced store ----
    {
        const float* dst = (const float*)(smem + DST);
        float* outg = out + ((size_t)(n * 128 + g * 16)) * 262144;
#pragma unroll
        for (int k = 0; k < 8; ++k) {
            int id = tid + k * THREADS;          // 4096 pair-items
            int c = id & 15;
            int r = (id >> 4) & 7;
            int py = (id >> 7) & 1;
            int oc = id >> 8;
            int p = r * 16 + c;
            float v0 = dst[p * DST_STR + (py * 2 + 0) * 16 + oc];
            float v1 = dst[p * DST_STR + (py * 2 + 1) * 16 + oc];
            float* o = outg + ((size_t)oc * 512 + (2 * (m0 + r) + py)) * 512 + 2 * (c0 + c);
            *(float2*)o = make_float2(v0, v1);
        }
    }
}

extern "C" void kernel_launch(void* const* d_in, const int* in_sizes, int n_in,
                              void* d_out, int out_size) {
    const float* x = (const float*)d_in[0];
    const float* f = (const float*)d_in[1];
    const float* w = (const float*)d_in[2];
    float* out = (float*)d_out;

    prep_weff<<<40, 512>>>(f, w);

    cudaFuncSetAttribute(conv_mma_kernel,
                         cudaFuncAttributeMaxDynamicSharedMemorySize, SMEM_BYTES);
    dim3 grid(512, 8, 4);    // spatial tiles (32x16), groups, batch
    conv_mma_kernel<<<grid, THREADS, SMEM_BYTES>>>(x, out);
}

// round 9
// speedup vs baseline: 2.8785x; 2.8785x over previous
#include <cuda_runtime.h>
#include <cstdint>

typedef unsigned long long ull;
#define THREADS 256   // placeholder comment; real value below

#undef THREADS
#define THREADS 512

// tile: 14x14 low-res -> 28x28 output
// smem: xb float [16 ic][17 r][18 pad]        @ 0      = 19584 B
//       wb ull2  [16 ic][8 op][5 pairs]       @ 19584  = 10240 B
//       z2 ull   [8 op][32 zr][36 (zeta,pad)] @ 29824  = 73728 B
#define XB_R   18
#define WB_OFF 19584
#define Z2_OFF 29824
#define Z2_ROW 36
#define Z2_OP  (32 * Z2_ROW)
#define SMEM_BYTES 103552

__device__ __forceinline__ ull pack2(float v) {
    ull r; asm("mov.b64 %0, {%1, %1};" : "=l"(r) : "f"(v)); return r;
}
__device__ __forceinline__ ull packf2(float a, float b) {
    ull r; asm("mov.b64 %0, {%1, %2};" : "=l"(r) : "f"(a), "f"(b)); return r;
}
__device__ __forceinline__ void fma2(ull &acc, ull a, ull b) {
    asm("fma.rn.f32x2 %0, %1, %2, %0;" : "+l"(acc) : "l"(a), "l"(b));
}

__global__ __launch_bounds__(THREADS, 2)
void conv_resample_v9(const float* __restrict__ x, const float* __restrict__ f,
                      const float* __restrict__ w, float* __restrict__ out) {
    extern __shared__ char sm[];
    float* xb = (float*)sm;
    ulonglong2* wb = (ulonglong2*)(sm + WB_OFF);
    ull* zb = (ull*)(sm + Z2_OFF);

    const int tid = threadIdx.x;
    const int wid = tid >> 5, ln = tid & 31;
    const int rt = blockIdx.x / 19, ct = blockIdx.x % 19;
    const int g = blockIdx.y, n = blockIdx.z;
    const int a0 = rt * 14, b0 = ct * 14;

    // ---- stage 1: x tile [16 ic][17][17] with zero halo ----
    const float* xg = x + ((size_t)(n * 128 + g * 16)) * 65536;
    for (int i = tid; i < 16 * 17 * 17; i += THREADS) {
        int c = i % 17;
        int rr = (i / 17) % 17;
        int ic = i / 289;
        int gm = a0 - 2 + rr, gq = b0 - 2 + c;
        float v = (gm >= 0 && gm < 256 && gq >= 0 && gq < 256)
                    ? xg[ic * 65536 + gm * 256 + gq] : 0.f;
        xb[(ic * 17 + rr) * XB_R + c] = v;
    }
    // ---- weights: oc-pair f32x2 in paired ull2 [ic][op][5]:
    //      j0=(w0,w1) j1=(w2,w6) j2=(w7,w8) j3=(w3,w5) j4=(w4,0) ----
    {
        const int lt[5] = {0, 2, 7, 3, 4};
        const int ht[5] = {1, 6, 8, 5, 0};
        const float* wgp = w + (size_t)g * 16 * 144;
        for (int i = tid; i < 16 * 8 * 5; i += THREADS) {
            int j = i % 5;
            int op = (i / 5) & 7;
            int ic = i / 40;
            const float* w0 = wgp + (op * 2 + 0) * 144 + ic * 9;
            const float* w1 = wgp + (op * 2 + 1) * 144 + ic * 9;
            ulonglong2 pr;
            pr.x = packf2(w0[lt[j]], w1[lt[j]]);
            pr.y = (j == 4) ? 0ull : packf2(w0[ht[j]], w1[ht[j]]);
            wb[i] = pr;
        }
    }
    float f0 = __ldg(f), f1 = __ldg(f + 1), f2 = __ldg(f + 2), f3 = __ldg(f + 3);
    ull gq0 = pack2(2.f * f3), gq1 = pack2(2.f * f2),
        gq2 = pack2(2.f * f1), gq3 = pack2(2.f * f0);
    __syncthreads();

    // ---- stage 2: 16 units = (4 op-groups) x (4 row-blocks); lane = (op-half, 16 cols) ----
    {
        const int opg = wid & 3, rb = wid >> 2;
        const int op = opg * 2 + (ln >> 4);
        const int pc = ln & 15;
        const int ar0 = rb * 4;

        ull acc[4][4];
#pragma unroll
        for (int r = 0; r < 4; ++r) { acc[r][0] = acc[r][1] = acc[r][2] = acc[r][3] = 0ull; }

#pragma unroll 4
        for (int ic = 0; ic < 16; ++ic) {
            const ulonglong2* wp = wb + (ic * 8 + op) * 5;
            ulonglong2 W0 = wp[0];   // (w0, w1)
            ulonglong2 W1 = wp[1];   // (w2, w6)
            ulonglong2 W2 = wp[2];   // (w7, w8)
            ulonglong2 W3 = wp[3];   // (w3, w5)
            ull W4 = wp[4].x;        // w4
            const float* xr = xb + (ic * 17 + ar0) * XB_R + pc;
            ull xa = pack2(xr[0]), xbv = pack2(xr[1]);
#pragma unroll
            for (int r = 0; r < 4; ++r) {
                ull ya = pack2(xr[(r + 1) * XB_R]);
                ull yb = pack2(xr[(r + 1) * XB_R + 1]);
                fma2(acc[r][0], xa,  W0.x); fma2(acc[r][0], xbv, W1.x);
                fma2(acc[r][0], ya,  W1.y); fma2(acc[r][0], yb,  W2.y);
                fma2(acc[r][1], xbv, W0.y); fma2(acc[r][1], yb,  W2.x);
                fma2(acc[r][2], ya,  W3.x); fma2(acc[r][2], yb,  W3.y);
                fma2(acc[r][3], yb,  W4);
                xa = ya; xbv = yb;
            }
        }
        // interleaved-zeta store: (py, row) -> zr = 2*(ar0+r)+py ; zeta = 2*pc (+1)
        ull* zo = zb + (size_t)op * Z2_OP + 2 * pc;
#pragma unroll
        for (int r = 0; r < 4; ++r) {
            int zr0 = 2 * (ar0 + r);
            ulonglong2 e0; e0.x = acc[r][0]; e0.y = acc[r][1];   // py0: (px0, px1)
            ulonglong2 e1; e1.x = acc[r][2]; e1.y = acc[r][3];   // py1
            *(ulonglong2*)(zo + (size_t)zr0 * Z2_ROW)       = e0;
            *(ulonglong2*)(zo + (size_t)(zr0 + 1) * Z2_ROW) = e1;
        }
    }
    __syncthreads();

    // ---- stage 3: vertical FIR with register ring; warp = (op, row-half), lane = out col ----
    {
        const int op3 = wid & 7, rh = wid >> 3;
        const int oy0 = rh * 14;
        const bool lane_ok = (ln < 28);
        const int oxc = lane_ok ? ln : 27;

        const ull* zp = zb + (size_t)op3 * Z2_OP + (size_t)(oy0 + 1) * Z2_ROW + (oxc + 1);
        ull tb0, tb1, tb2;
        { ull t = 0; fma2(t, zp[0], gq0); fma2(t, zp[1], gq1);
          fma2(t, zp[2], gq2); fma2(t, zp[3], gq3); tb0 = t; zp += Z2_ROW; }
        { ull t = 0; fma2(t, zp[0], gq0); fma2(t, zp[1], gq1);
          fma2(t, zp[2], gq2); fma2(t, zp[3], gq3); tb1 = t; zp += Z2_ROW; }
        { ull t = 0; fma2(t, zp[0], gq0); fma2(t, zp[1], gq1);
          fma2(t, zp[2], gq2); fma2(t, zp[3], gq3); tb2 = t; zp += Z2_ROW; }

        const bool col_ok = lane_ok && (2 * b0 + ln < 512);
        float* og = out + ((size_t)(n * 128 + g * 16 + op3 * 2)) * 262144
                        + (size_t)(2 * a0) * 512 + 2 * b0;

#pragma unroll 7
        for (int oyl = 0; oyl < 14; ++oyl) {
            ull t = 0;
            fma2(t, zp[0], gq0); fma2(t, zp[1], gq1);
            fma2(t, zp[2], gq2); fma2(t, zp[3], gq3);
            zp += Z2_ROW;
            ull y = 0;
            fma2(y, tb0, gq0); fma2(y, tb1, gq1);
            fma2(y, tb2, gq2); fma2(y, t, gq3);
            tb0 = tb1; tb1 = tb2; tb2 = t;
            int oy = oy0 + oyl;
            if (col_ok && (2 * a0 + oy < 512)) {
                float2 yy = *(float2*)&y;
                size_t o = (size_t)oy * 512 + ln;
                og[o] = yy.x;
                og[o + 262144] = yy.y;
            }
        }
    }
}

extern "C" void kernel_launch(void* const* d_in, const int* in_sizes, int n_in,
                              void* d_out, int out_size) {
    const float* x = (const float*)d_in[0];
    const float* f = (const float*)d_in[1];
    const float* w = (const float*)d_in[2];
    float* out = (float*)d_out;

    cudaFuncSetAttribute(conv_resample_v9,
                         cudaFuncAttributeMaxDynamicSharedMemorySize, SMEM_BYTES);
    dim3 grid(19 * 19, 8, 4);   // 361 tiles x groups x batch = 11552 CTAs
    conv_resample_v9<<<grid, THREADS, SMEM_BYTES>>>(x, f, w, out);
}